// round 14
// baseline (speedup 1.0000x reference)
#include <cuda_runtime.h>
#include <cuda_fp16.h>
#include <math.h>
#include <stdint.h>

// ---------------------------------------------------------------------------
// B=8, images 3x1024x1024, backbone conv 3x3 s16 p1 -> 64x64, avgpool2 -> 32x32
// f: (8,32,32,256) NHWC. Only h=0, w=0..3 of the RPN matter (first 100 props).
// ROI align: 800 boxes -> x (800,12544), k' = s*256+c permutation, emitted as
// fp16 hi/lo split. fc1/fc2 run on mma.sync tensor cores (fp16x3 split).
// NOTE: toolchain targets sm_103 (no 'a') => tcgen05 PTX is rejected; the
// warp-level HMMA path (ldmatrix + mma.sync, compute_80 PTX) is the tensor
// route available here.
// Output: class_logits (800x5) then obb_preds (800x5) = 8000 floats.
// ---------------------------------------------------------------------------

#define BATCH 8
#define CF 256
#define HF 32
#define WF 32
#define NPROP 100
#define NBOX (BATCH * NPROP)   // 800
#define KDIM (CF * 49)         // 12544
#define MPAD 896               // 7 * 128
#define NFC 1024

__device__ float g_f[BATCH * HF * WF * CF];          // NHWC feature map
__device__ float g_boxes[NBOX * 5];
__device__ __half g_xh[MPAD * KDIM];                 // pooled hi (rows 800.. stay 0)
__device__ __half g_xl[MPAD * KDIM];                 // pooled lo
__device__ __half g_w1h[NFC * KDIM];                 // permuted fc1 weights hi
__device__ __half g_w1l[NFC * KDIM];
__device__ __half g_w2h[NFC * NFC];
__device__ __half g_w2l[NFC * NFC];
__device__ __half g_h1h[MPAD * NFC];
__device__ __half g_h1l[MPAD * NFC];
__device__ float g_h2[MPAD * NFC];

// ---------------------------------------------------------------------------
// Kernel 1: backbone conv (3x3, stride16, pad1) + 2x2 avgpool, fused. NHWC out.
// ---------------------------------------------------------------------------
__global__ void __launch_bounds__(256) backbone_kernel(
    const float* __restrict__ images, const float* __restrict__ wconv,
    const float* __restrict__ bconv)
{
    __shared__ float in_s[3][6][192];
    const int ph = blockIdx.x;
    const int b  = blockIdx.y;
    const int t  = threadIdx.x;

    for (int e = t; e < 3 * 6 * 192; e += 256) {
        int ch = e / 1152;
        int r  = (e / 192) % 6;
        int q  = e % 192;
        int ow = q / 3, kx = q % 3;
        int row = (r < 3) ? (32 * ph - 1 + r) : (32 * ph + 15 + (r - 3));
        int col = 16 * ow + kx - 1;
        float v = 0.f;
        if (row >= 0 && col >= 0)
            v = images[(((size_t)b * 3 + ch) * 1024 + row) * 1024 + col];
        in_s[ch][r][q] = v;
    }
    __syncthreads();

    const int oc = t;
    float wr[27];
#pragma unroll
    for (int j = 0; j < 27; j++) wr[j] = wconv[oc * 27 + j];
    const float bias = bconv[oc];

    for (int pw = 0; pw < 32; pw++) {
        float acc = 0.f;
#pragma unroll
        for (int sub = 0; sub < 4; sub++) {
            int r6b = (sub >> 1) * 3;
            int owp = 2 * pw + (sub & 1);
#pragma unroll
            for (int ch = 0; ch < 3; ch++)
#pragma unroll
                for (int ky = 0; ky < 3; ky++)
#pragma unroll
                    for (int kx = 0; kx < 3; kx++)
                        acc += wr[ch * 9 + ky * 3 + kx] * in_s[ch][r6b + ky][owp * 3 + kx];
        }
        g_f[(((size_t)b * HF + ph) * WF + pw) * CF + oc] = acc * 0.25f + bias;
    }
}

// ---------------------------------------------------------------------------
// Kernel 2: RPN conv (only h=0, w=0..3) + delta head + proposal decode.
// ---------------------------------------------------------------------------
__global__ void __launch_bounds__(256) rpn_decode_kernel(
    const float* __restrict__ rpn_w, const float* __restrict__ rpn_b,
    const float* __restrict__ delta_w, const float* __restrict__ delta_b)
{
    __shared__ float fin[2][3][256];
    __shared__ float t_s[256];
    __shared__ float d_s[135];

    const int b = blockIdx.x >> 2;
    const int w = blockIdx.x & 3;
    const int t = threadIdx.x;

    for (int e = t; e < 2 * 3 * 256; e += 256) {
        int iy = e / 768;
        int rem = e % 768;
        int cx = rem / 256;
        int c  = rem % 256;
        int col = w + cx - 1;
        float v = 0.f;
        if (col >= 0 && col < WF)
            v = g_f[(((size_t)b * HF + iy) * WF + col) * CF + c];
        fin[iy][cx][c] = v;
    }
    __syncthreads();

    {
        const int oc = t;
        float acc = rpn_b[oc];
        for (int c = 0; c < 256; c++) {
            const float* wp = rpn_w + ((size_t)oc * 256 + c) * 9;
#pragma unroll
            for (int ky = 1; ky < 3; ky++)
#pragma unroll
                for (int kx = 0; kx < 3; kx++)
                    acc += wp[ky * 3 + kx] * fin[ky - 1][kx][c];
        }
        t_s[oc] = fmaxf(acc, 0.f);
    }
    __syncthreads();

    if (t < 135) {
        float acc = delta_b[t];
        const float* wp = delta_w + (size_t)t * 256;
        for (int c = 0; c < 256; c++) acc += wp[c] * t_s[c];
        d_s[t] = acc;
    }
    __syncthreads();

    if (t < 27) {
        int a = t;
        int p = w * 27 + a;
        if (p < NPROP) {
            int si = a / 9, ri = (a % 9) / 3, angi = a % 3;
            float scale = 32.f * (float)(1 << si);
            float sr = (ri == 0) ? 0.70710678118654752f : (ri == 1 ? 1.f : 1.41421356237309505f);
            float aw = scale * sr;
            float ah = scale / sr;
            float aang = 45.f * (float)angi;
            float acx = 32.f * (float)w;
            float d0 = d_s[a * 5 + 0], d1 = d_s[a * 5 + 1], d2 = d_s[a * 5 + 2];
            float d3 = d_s[a * 5 + 3], d4 = d_s[a * 5 + 4];
            float* bx = g_boxes + ((size_t)b * NPROP + p) * 5;
            bx[0] = d0 * aw + acx;
            bx[1] = d1 * ah;
            bx[2] = expf(d2) * aw;
            bx[3] = expf(d3) * ah;
            bx[4] = aang + d4;
        }
    }
}

// ---------------------------------------------------------------------------
// Kernel 3: rotated ROI align -> fp16 hi/lo split, k' = s*256+c layout.
// ---------------------------------------------------------------------------
__global__ void __launch_bounds__(256) roi_align_kernel()
{
    __shared__ int   sx0[49], sy0[49], sx1[49], sy1[49];
    __shared__ float sw00[49], sw10[49], sw01[49], sw11[49];

    const int n = blockIdx.x;
    const int b = n / NPROP;
    const int t = threadIdx.x;

    if (t < 49) {
        int py = t / 7, px = t % 7;
        const float* bx = g_boxes + (size_t)n * 5;
        float cx = bx[0], cy = bx[1], w = bx[2], h = bx[3], ang = bx[4];
        float ar = -ang * 0.017453292519943295f;
        float cc = cosf(ar), ss = sinf(ar);
        float t00 = w * (1.f / WF) * cc;
        float t01 = -h * (1.f / HF) * ss;
        float t02 = 2.f * cx / WF - 1.f;
        float t10 = w * (1.f / WF) * ss;
        float t11 = h * (1.f / HF) * cc;
        float t12 = 2.f * cy / HF - 1.f;
        float xs = (2.f * px + 1.f) / 7.f - 1.f;
        float ys = (2.f * py + 1.f) / 7.f - 1.f;
        float gx = t00 * xs + t01 * ys + t02;
        float gy = t10 * xs + t11 * ys + t12;
        float ix = ((gx + 1.f) * WF - 1.f) * 0.5f;
        float iy = ((gy + 1.f) * HF - 1.f) * 0.5f;
        float x0f = floorf(ix), y0f = floorf(iy);
        float wx = ix - x0f, wy = iy - y0f;
        int x0 = (int)x0f, y0 = (int)y0f;
        int x1 = x0 + 1, y1 = y0 + 1;
        float vx0 = (x0 >= 0 && x0 < WF) ? 1.f : 0.f;
        float vx1 = (x1 >= 0 && x1 < WF) ? 1.f : 0.f;
        float vy0 = (y0 >= 0 && y0 < HF) ? 1.f : 0.f;
        float vy1 = (y1 >= 0 && y1 < HF) ? 1.f : 0.f;
        sw00[t] = (1.f - wx) * (1.f - wy) * vx0 * vy0;
        sw10[t] = wx * (1.f - wy) * vx1 * vy0;
        sw01[t] = (1.f - wx) * wy * vx0 * vy1;
        sw11[t] = wx * wy * vx1 * vy1;
        sx0[t] = min(max(x0, 0), WF - 1);
        sx1[t] = min(max(x1, 0), WF - 1);
        sy0[t] = min(max(y0, 0), HF - 1);
        sy1[t] = min(max(y1, 0), HF - 1);
    }
    __syncthreads();

    const int c = t;
    const float* fb = g_f + (size_t)b * HF * WF * CF;
    __half* xh = g_xh + (size_t)n * KDIM;
    __half* xl = g_xl + (size_t)n * KDIM;
#pragma unroll 7
    for (int s = 0; s < 49; s++) {
        int x0 = sx0[s], x1 = sx1[s], y0 = sy0[s], y1 = sy1[s];
        float v = sw00[s] * fb[(y0 * WF + x0) * CF + c]
                + sw10[s] * fb[(y0 * WF + x1) * CF + c]
                + sw01[s] * fb[(y1 * WF + x0) * CF + c]
                + sw11[s] * fb[(y1 * WF + x1) * CF + c];
        __half hi = __float2half(v);
        xh[s * 256 + c] = hi;
        xl[s * 256 + c] = __float2half(v - __half2float(hi));
    }
}

// ---------------------------------------------------------------------------
// Kernel 4: permute fc1 weights + fp16 split: W1[j, s*256+c] = fc1_w[j, c*49+s]
// ---------------------------------------------------------------------------
__global__ void __launch_bounds__(256) permute_w1_kernel(const float* __restrict__ w1)
{
    __shared__ float sm[128 * 49];
    const int j = blockIdx.x >> 1;
    const int c0 = (blockIdx.x & 1) * 128;
    const int t = threadIdx.x;

    const float* src = w1 + (size_t)j * KDIM + (size_t)c0 * 49;
    for (int i = t; i < 128 * 49; i += 256) sm[i] = src[i];
    __syncthreads();

    __half* dh = g_w1h + (size_t)j * KDIM;
    __half* dl = g_w1l + (size_t)j * KDIM;
    for (int e = t; e < 49 * 128; e += 256) {
        int s = e / 128;
        int cl = e % 128;
        float v = sm[cl * 49 + s];
        __half hi = __float2half(v);
        dh[s * 256 + c0 + cl] = hi;
        dl[s * 256 + c0 + cl] = __float2half(v - __half2float(hi));
    }
}

// ---------------------------------------------------------------------------
// Kernel 4b: fc2 weight fp16 split (no permute needed).
// ---------------------------------------------------------------------------
__global__ void __launch_bounds__(256) split_w2_kernel(const float* __restrict__ w2)
{
    int i = blockIdx.x * 256 + threadIdx.x;
    float v = w2[i];
    __half hi = __float2half(v);
    g_w2h[i] = hi;
    g_w2l[i] = __float2half(v - __half2float(hi));
}

// ---------------------------------------------------------------------------
// Kernel 5: mma.sync GEMM, fp16x3-split fp32-accuracy.
// C[m,n] = relu( sum_k A[m,k]*B[n,k] + bias[n] ),  C row stride = NFC.
// CTA tile 128(M) x 64(N), BK=64, 128 threads, 4 warps (warp tile 64x32).
// mode 0: write fp32 to Cf.  mode 1: write fp16 hi/lo to Ch/Cl.
// ---------------------------------------------------------------------------
#define RSTRIDE 144                       // (64+8) halves * 2 bytes, pad kills LDSM conflicts
#define A_TILE (128 * RSTRIDE)            // 18432 B
#define B_TILE (64 * RSTRIDE)             // 9216 B
#define AH_OFF 0
#define AL_OFF A_TILE
#define BH_OFF (2 * A_TILE)
#define BL_OFF (2 * A_TILE + B_TILE)
#define STAGE_B (2 * A_TILE + 2 * B_TILE) // 55296 B
#define GEMM_SMEM (2 * STAGE_B)           // 110592 B

__device__ __forceinline__ uint32_t smem_u32(const void* p) {
    uint32_t a;
    asm("{ .reg .u64 t; cvta.to.shared.u64 t, %1; cvt.u32.u64 %0, t; }" : "=r"(a) : "l"(p));
    return a;
}
__device__ __forceinline__ void cp16(uint32_t dst, const void* src) {
    asm volatile("cp.async.cg.shared.global [%0], [%1], 16;" :: "r"(dst), "l"(src) : "memory");
}
#define LDSM4(R, addr) \
    asm volatile("ldmatrix.sync.aligned.m8n8.x4.shared.b16 {%0,%1,%2,%3}, [%4];" \
                 : "=r"((R)[0]), "=r"((R)[1]), "=r"((R)[2]), "=r"((R)[3]) : "r"(addr))

__device__ __forceinline__ void mma16816(float* d, const uint32_t* a, const uint32_t* b) {
    asm volatile(
        "mma.sync.aligned.m16n8k16.row.col.f32.f16.f16.f32 "
        "{%0,%1,%2,%3}, {%4,%5,%6,%7}, {%8,%9}, {%0,%1,%2,%3};"
        : "+f"(d[0]), "+f"(d[1]), "+f"(d[2]), "+f"(d[3])
        : "r"(a[0]), "r"(a[1]), "r"(a[2]), "r"(a[3]), "r"(b[0]), "r"(b[1]));
}

__device__ __forceinline__ void load_chunk(
    uint32_t st, const __half* __restrict__ Ah, const __half* __restrict__ Al,
    const __half* __restrict__ Bh, const __half* __restrict__ Bl,
    int m0, int n0, int K, int k0, int t)
{
#pragma unroll
    for (int e = t; e < 1024; e += 128) {          // A: 128 rows x 8 segs
        int r = e >> 3, s = e & 7;
        size_t g = (size_t)(m0 + r) * K + k0 + s * 8;
        uint32_t d = (uint32_t)(r * RSTRIDE + s * 16);
        cp16(st + AH_OFF + d, Ah + g);
        cp16(st + AL_OFF + d, Al + g);
    }
#pragma unroll
    for (int e = t; e < 512; e += 128) {           // B: 64 rows x 8 segs
        int r = e >> 3, s = e & 7;
        size_t g = (size_t)(n0 + r) * K + k0 + s * 8;
        uint32_t d = (uint32_t)(r * RSTRIDE + s * 16);
        cp16(st + BH_OFF + d, Bh + g);
        cp16(st + BL_OFF + d, Bl + g);
    }
}

__global__ void __launch_bounds__(128, 1) gemm_mma_kernel(
    const __half* __restrict__ Ah, const __half* __restrict__ Al,
    const __half* __restrict__ Bh, const __half* __restrict__ Bl,
    const float* __restrict__ bias, float* __restrict__ Cf,
    __half* __restrict__ Ch, __half* __restrict__ Cl, int K, int mode)
{
    extern __shared__ char smem[];
    const uint32_t sb = smem_u32(smem);
    const int t = threadIdx.x;
    const int m0 = blockIdx.y * 128;
    const int n0 = blockIdx.x * 64;

    const int w = t >> 5, l = t & 31;
    const int wm = (w >> 1) * 64;                 // warp M offset in CTA tile
    const int wn = (w & 1) * 32;                  // warp N offset
    // ldmatrix lane-address components
    const int a_m  = (l & 7) + ((l >> 3) & 1) * 8;
    const int a_ks = (l >> 4) * 16;               // byte offset for k-segment
    const int b_n  = (l & 7) + (l >> 4) * 8;
    const int b_ks = ((l >> 3) & 1) * 16;

    float acc[4][4][4];
#pragma unroll
    for (int i = 0; i < 4; i++)
#pragma unroll
        for (int j = 0; j < 4; j++)
#pragma unroll
            for (int q = 0; q < 4; q++) acc[i][j][q] = 0.f;

    const int nit = K >> 6;
    load_chunk(sb, Ah, Al, Bh, Bl, m0, n0, K, 0, t);
    asm volatile("cp.async.commit_group;" ::: "memory");

    for (int i = 0; i < nit; i++) {
        if (i + 1 < nit) {
            load_chunk(sb + ((i + 1) & 1) * STAGE_B, Ah, Al, Bh, Bl,
                       m0, n0, K, (i + 1) << 6, t);
            asm volatile("cp.async.commit_group;" ::: "memory");
            asm volatile("cp.async.wait_group 1;" ::: "memory");
        } else {
            asm volatile("cp.async.wait_group 0;" ::: "memory");
        }
        __syncthreads();

        const uint32_t st = sb + (i & 1) * STAGE_B;
#pragma unroll
        for (int kk = 0; kk < 4; kk++) {
            const uint32_t kb = (uint32_t)(kk * 32);
            uint32_t ah[4][4], al[4][4], bh[2][4], bl[2][4];
#pragma unroll
            for (int mt = 0; mt < 4; mt++) {
                uint32_t row = (uint32_t)((wm + mt * 16 + a_m) * RSTRIDE) + kb + a_ks;
                LDSM4(ah[mt], st + AH_OFF + row);
                LDSM4(al[mt], st + AL_OFF + row);
            }
#pragma unroll
            for (int np = 0; np < 2; np++) {
                uint32_t row = (uint32_t)((wn + np * 16 + b_n) * RSTRIDE) + kb + b_ks;
                LDSM4(bh[np], st + BH_OFF + row);
                LDSM4(bl[np], st + BL_OFF + row);
            }
#pragma unroll
            for (int mt = 0; mt < 4; mt++)
#pragma unroll
                for (int nt = 0; nt < 4; nt++) {
                    const uint32_t* bhp = &bh[nt >> 1][(nt & 1) * 2];
                    const uint32_t* blp = &bl[nt >> 1][(nt & 1) * 2];
                    mma16816(acc[mt][nt], ah[mt], bhp);
                    mma16816(acc[mt][nt], ah[mt], blp);
                    mma16816(acc[mt][nt], al[mt], bhp);
                }
        }
        __syncthreads();
    }

    // epilogue: bias + relu, write
#pragma unroll
    for (int mt = 0; mt < 4; mt++) {
        const int mrow = m0 + wm + mt * 16 + (l >> 2);
#pragma unroll
        for (int nt = 0; nt < 4; nt++) {
            const int ncol = n0 + wn + nt * 8 + (l & 3) * 2;
            const float b0 = bias[ncol], b1 = bias[ncol + 1];
            float v0 = fmaxf(acc[mt][nt][0] + b0, 0.f);
            float v1 = fmaxf(acc[mt][nt][1] + b1, 0.f);
            float v2 = fmaxf(acc[mt][nt][2] + b0, 0.f);
            float v3 = fmaxf(acc[mt][nt][3] + b1, 0.f);
            size_t i0 = (size_t)mrow * NFC + ncol;
            size_t i1 = (size_t)(mrow + 8) * NFC + ncol;
            if (mode == 0) {
                Cf[i0] = v0; Cf[i0 + 1] = v1;
                Cf[i1] = v2; Cf[i1 + 1] = v3;
            } else {
                __half h0 = __float2half(v0), h1v = __float2half(v1);
                __half h2v = __float2half(v2), h3 = __float2half(v3);
                Ch[i0] = h0;  Ch[i0 + 1] = h1v;
                Ch[i1] = h2v; Ch[i1 + 1] = h3;
                Cl[i0] = __float2half(v0 - __half2float(h0));
                Cl[i0 + 1] = __float2half(v1 - __half2float(h1v));
                Cl[i1] = __float2half(v2 - __half2float(h2v));
                Cl[i1 + 1] = __float2half(v3 - __half2float(h3));
            }
        }
    }
}

// ---------------------------------------------------------------------------
// Kernel 6: heads. grid 800, 320 threads (10 warps = 10 outputs).
// ---------------------------------------------------------------------------
__global__ void __launch_bounds__(320) heads_kernel(
    const float* __restrict__ cls_w, const float* __restrict__ cls_b,
    const float* __restrict__ bbox_w, const float* __restrict__ bbox_b,
    float* __restrict__ out)
{
    const int n = blockIdx.x;
    const int warp = threadIdx.x >> 5;
    const int lane = threadIdx.x & 31;

    const float* W = (warp < 5) ? (cls_w + (size_t)warp * NFC)
                                : (bbox_w + (size_t)(warp - 5) * NFC);
    const float  bb = (warp < 5) ? cls_b[warp] : bbox_b[warp - 5];
    const float* hr = g_h2 + (size_t)n * NFC;

    float acc = 0.f;
    for (int k = lane; k < NFC; k += 32) acc += hr[k] * W[k];
#pragma unroll
    for (int o = 16; o > 0; o >>= 1) acc += __shfl_down_sync(0xffffffffu, acc, o);

    if (lane == 0) {
        float v = acc + bb;
        if (warp < 5) out[(size_t)n * 5 + warp] = v;
        else          out[4000 + (size_t)n * 5 + (warp - 5)] = v;
    }
}

// ---------------------------------------------------------------------------
extern "C" void kernel_launch(void* const* d_in, const int* in_sizes, int n_in,
                              void* d_out, int out_size)
{
    const float* images     = (const float*)d_in[0];
    const float* backbone_w = (const float*)d_in[1];
    const float* backbone_b = (const float*)d_in[2];
    const float* rpn_conv_w = (const float*)d_in[3];
    const float* rpn_conv_b = (const float*)d_in[4];
    // d_in[5], d_in[6]: obj head — dead code in the reference
    const float* delta_w    = (const float*)d_in[7];
    const float* delta_b    = (const float*)d_in[8];
    const float* fc1_w      = (const float*)d_in[9];
    const float* fc1_b      = (const float*)d_in[10];
    const float* fc2_w      = (const float*)d_in[11];
    const float* fc2_b      = (const float*)d_in[12];
    const float* cls_w      = (const float*)d_in[13];
    const float* cls_b      = (const float*)d_in[14];
    const float* bbox_w     = (const float*)d_in[15];
    const float* bbox_b     = (const float*)d_in[16];
    float* out = (float*)d_out;

    __half *xh, *xl, *w1h, *w1l, *w2h, *w2l, *h1h, *h1l;
    float *h2;
    cudaGetSymbolAddress((void**)&xh,  g_xh);
    cudaGetSymbolAddress((void**)&xl,  g_xl);
    cudaGetSymbolAddress((void**)&w1h, g_w1h);
    cudaGetSymbolAddress((void**)&w1l, g_w1l);
    cudaGetSymbolAddress((void**)&w2h, g_w2h);
    cudaGetSymbolAddress((void**)&w2l, g_w2l);
    cudaGetSymbolAddress((void**)&h1h, g_h1h);
    cudaGetSymbolAddress((void**)&h1l, g_h1l);
    cudaGetSymbolAddress((void**)&h2,  g_h2);

    static int smem_set = 0;
    if (!smem_set) {
        cudaFuncSetAttribute(gemm_mma_kernel,
                             cudaFuncAttributeMaxDynamicSharedMemorySize, GEMM_SMEM);
        smem_set = 1;
    }

    // 1. backbone + avgpool -> g_f (NHWC)
    backbone_kernel<<<dim3(32, 8), 256>>>(images, backbone_w, backbone_b);

    // 2. RPN (4 positions) + decode -> g_boxes
    rpn_decode_kernel<<<32, 256>>>(rpn_conv_w, rpn_conv_b, delta_w, delta_b);

    // 3. ROI align -> xh/xl (fp16 split, permuted k layout)
    roi_align_kernel<<<NBOX, 256>>>();

    // 4. weight prep
    permute_w1_kernel<<<2048, 256>>>(fc1_w);
    split_w2_kernel<<<(NFC * NFC) / 256, 256>>>(fc2_w);

    // 5. fc1: (896 x 12544) @ (1024 x 12544)^T + bias, relu -> h1 (fp16 split)
    gemm_mma_kernel<<<dim3(NFC / 64, MPAD / 128), 128, GEMM_SMEM>>>(
        xh, xl, w1h, w1l, fc1_b, h2 /*unused*/, h1h, h1l, KDIM, 1);

    // 6. fc2: (896 x 1024) @ (1024 x 1024)^T + bias, relu -> h2 (fp32)
    gemm_mma_kernel<<<dim3(NFC / 64, MPAD / 128), 128, GEMM_SMEM>>>(
        h1h, h1l, w2h, w2l, fc2_b, h2, h1h /*unused*/, h1l /*unused*/, NFC, 0);

    // 7. heads -> out
    heads_kernel<<<NBOX, 320>>>(cls_w, cls_b, bbox_w, bbox_b, out);
}

// round 15
// speedup vs baseline: 1.9710x; 1.9710x over previous
#include <cuda_runtime.h>
#include <cuda_fp16.h>
#include <math.h>
#include <stdint.h>

// ---------------------------------------------------------------------------
// B=8, images 3x1024x1024, backbone conv 3x3 s16 p1 -> 64x64, avgpool2 -> 32x32
// f: (8,32,32,256) NHWC. Only h=0, w=0..3 of the RPN matter (first 100 props).
// ROI align: 800 boxes -> x (800,12544), k' = s*256+c permutation, fp16 hi/lo.
// fc1/fc2 on mma.sync tensor cores with 2-term split: AhBh + AlBh (weights
// rounded once to fp16; dropped AhBl term is a ~1.4e-4 random-walk error,
// inside the 1e-3 gate). tcgen05 is unavailable: toolchain targets sm_103.
// Output: class_logits (800x5) then obb_preds (800x5) = 8000 floats.
// ---------------------------------------------------------------------------

#define BATCH 8
#define CF 256
#define HF 32
#define WF 32
#define NPROP 100
#define NBOX (BATCH * NPROP)   // 800
#define KDIM (CF * 49)         // 12544
#define MPAD 896               // 14 * 64
#define NFC 1024

__device__ float g_f[BATCH * HF * WF * CF];          // NHWC feature map
__device__ float g_boxes[NBOX * 5];
__device__ __half g_xh[MPAD * KDIM];                 // pooled hi (rows 800.. stay 0)
__device__ __half g_xl[MPAD * KDIM];                 // pooled lo
__device__ __half g_w1h[NFC * KDIM];                 // permuted fc1 weights (hi only)
__device__ __half g_w2h[NFC * NFC];                  // fc2 weights (hi only)
__device__ __half g_h1h[MPAD * NFC];
__device__ __half g_h1l[MPAD * NFC];
__device__ float g_h2[MPAD * NFC];

// ---------------------------------------------------------------------------
// Kernel 1: backbone conv (3x3, stride16, pad1) + 2x2 avgpool, fused. NHWC out.
// ---------------------------------------------------------------------------
__global__ void __launch_bounds__(256) backbone_kernel(
    const float* __restrict__ images, const float* __restrict__ wconv,
    const float* __restrict__ bconv)
{
    __shared__ float in_s[3][6][192];
    const int ph = blockIdx.x;
    const int b  = blockIdx.y;
    const int t  = threadIdx.x;

    for (int e = t; e < 3 * 6 * 192; e += 256) {
        int ch = e / 1152;
        int r  = (e / 192) % 6;
        int q  = e % 192;
        int ow = q / 3, kx = q % 3;
        int row = (r < 3) ? (32 * ph - 1 + r) : (32 * ph + 15 + (r - 3));
        int col = 16 * ow + kx - 1;
        float v = 0.f;
        if (row >= 0 && col >= 0)
            v = images[(((size_t)b * 3 + ch) * 1024 + row) * 1024 + col];
        in_s[ch][r][q] = v;
    }
    __syncthreads();

    const int oc = t;
    float wr[27];
#pragma unroll
    for (int j = 0; j < 27; j++) wr[j] = wconv[oc * 27 + j];
    const float bias = bconv[oc];

    for (int pw = 0; pw < 32; pw++) {
        float acc = 0.f;
#pragma unroll
        for (int sub = 0; sub < 4; sub++) {
            int r6b = (sub >> 1) * 3;
            int owp = 2 * pw + (sub & 1);
#pragma unroll
            for (int ch = 0; ch < 3; ch++)
#pragma unroll
                for (int ky = 0; ky < 3; ky++)
#pragma unroll
                    for (int kx = 0; kx < 3; kx++)
                        acc += wr[ch * 9 + ky * 3 + kx] * in_s[ch][r6b + ky][owp * 3 + kx];
        }
        g_f[(((size_t)b * HF + ph) * WF + pw) * CF + oc] = acc * 0.25f + bias;
    }
}

// ---------------------------------------------------------------------------
// Kernel 2: RPN conv (only h=0, w=0..3) + delta head + proposal decode.
// ---------------------------------------------------------------------------
__global__ void __launch_bounds__(256) rpn_decode_kernel(
    const float* __restrict__ rpn_w, const float* __restrict__ rpn_b,
    const float* __restrict__ delta_w, const float* __restrict__ delta_b)
{
    __shared__ float fin[2][3][256];
    __shared__ float t_s[256];
    __shared__ float d_s[135];

    const int b = blockIdx.x >> 2;
    const int w = blockIdx.x & 3;
    const int t = threadIdx.x;

    for (int e = t; e < 2 * 3 * 256; e += 256) {
        int iy = e / 768;
        int rem = e % 768;
        int cx = rem / 256;
        int c  = rem % 256;
        int col = w + cx - 1;
        float v = 0.f;
        if (col >= 0 && col < WF)
            v = g_f[(((size_t)b * HF + iy) * WF + col) * CF + c];
        fin[iy][cx][c] = v;
    }
    __syncthreads();

    {
        const int oc = t;
        float acc = rpn_b[oc];
        for (int c = 0; c < 256; c++) {
            const float* wp = rpn_w + ((size_t)oc * 256 + c) * 9;
#pragma unroll
            for (int ky = 1; ky < 3; ky++)
#pragma unroll
                for (int kx = 0; kx < 3; kx++)
                    acc += wp[ky * 3 + kx] * fin[ky - 1][kx][c];
        }
        t_s[oc] = fmaxf(acc, 0.f);
    }
    __syncthreads();

    if (t < 135) {
        float acc = delta_b[t];
        const float* wp = delta_w + (size_t)t * 256;
        for (int c = 0; c < 256; c++) acc += wp[c] * t_s[c];
        d_s[t] = acc;
    }
    __syncthreads();

    if (t < 27) {
        int a = t;
        int p = w * 27 + a;
        if (p < NPROP) {
            int si = a / 9, ri = (a % 9) / 3, angi = a % 3;
            float scale = 32.f * (float)(1 << si);
            float sr = (ri == 0) ? 0.70710678118654752f : (ri == 1 ? 1.f : 1.41421356237309505f);
            float aw = scale * sr;
            float ah = scale / sr;
            float aang = 45.f * (float)angi;
            float acx = 32.f * (float)w;
            float d0 = d_s[a * 5 + 0], d1 = d_s[a * 5 + 1], d2 = d_s[a * 5 + 2];
            float d3 = d_s[a * 5 + 3], d4 = d_s[a * 5 + 4];
            float* bx = g_boxes + ((size_t)b * NPROP + p) * 5;
            bx[0] = d0 * aw + acx;
            bx[1] = d1 * ah;
            bx[2] = expf(d2) * aw;
            bx[3] = expf(d3) * ah;
            bx[4] = aang + d4;
        }
    }
}

// ---------------------------------------------------------------------------
// Kernel 3: rotated ROI align -> fp16 hi/lo split, k' = s*256+c layout.
// ---------------------------------------------------------------------------
__global__ void __launch_bounds__(256) roi_align_kernel()
{
    __shared__ int   sx0[49], sy0[49], sx1[49], sy1[49];
    __shared__ float sw00[49], sw10[49], sw01[49], sw11[49];

    const int n = blockIdx.x;
    const int b = n / NPROP;
    const int t = threadIdx.x;

    if (t < 49) {
        int py = t / 7, px = t % 7;
        const float* bx = g_boxes + (size_t)n * 5;
        float cx = bx[0], cy = bx[1], w = bx[2], h = bx[3], ang = bx[4];
        float ar = -ang * 0.017453292519943295f;
        float cc = cosf(ar), ss = sinf(ar);
        float t00 = w * (1.f / WF) * cc;
        float t01 = -h * (1.f / HF) * ss;
        float t02 = 2.f * cx / WF - 1.f;
        float t10 = w * (1.f / WF) * ss;
        float t11 = h * (1.f / HF) * cc;
        float t12 = 2.f * cy / HF - 1.f;
        float xs = (2.f * px + 1.f) / 7.f - 1.f;
        float ys = (2.f * py + 1.f) / 7.f - 1.f;
        float gx = t00 * xs + t01 * ys + t02;
        float gy = t10 * xs + t11 * ys + t12;
        float ix = ((gx + 1.f) * WF - 1.f) * 0.5f;
        float iy = ((gy + 1.f) * HF - 1.f) * 0.5f;
        float x0f = floorf(ix), y0f = floorf(iy);
        float wx = ix - x0f, wy = iy - y0f;
        int x0 = (int)x0f, y0 = (int)y0f;
        int x1 = x0 + 1, y1 = y0 + 1;
        float vx0 = (x0 >= 0 && x0 < WF) ? 1.f : 0.f;
        float vx1 = (x1 >= 0 && x1 < WF) ? 1.f : 0.f;
        float vy0 = (y0 >= 0 && y0 < HF) ? 1.f : 0.f;
        float vy1 = (y1 >= 0 && y1 < HF) ? 1.f : 0.f;
        sw00[t] = (1.f - wx) * (1.f - wy) * vx0 * vy0;
        sw10[t] = wx * (1.f - wy) * vx1 * vy0;
        sw01[t] = (1.f - wx) * wy * vx0 * vy1;
        sw11[t] = wx * wy * vx1 * vy1;
        sx0[t] = min(max(x0, 0), WF - 1);
        sx1[t] = min(max(x1, 0), WF - 1);
        sy0[t] = min(max(y0, 0), HF - 1);
        sy1[t] = min(max(y1, 0), HF - 1);
    }
    __syncthreads();

    const int c = t;
    const float* fb = g_f + (size_t)b * HF * WF * CF;
    __half* xh = g_xh + (size_t)n * KDIM;
    __half* xl = g_xl + (size_t)n * KDIM;
#pragma unroll 7
    for (int s = 0; s < 49; s++) {
        int x0 = sx0[s], x1 = sx1[s], y0 = sy0[s], y1 = sy1[s];
        float v = sw00[s] * fb[(y0 * WF + x0) * CF + c]
                + sw10[s] * fb[(y0 * WF + x1) * CF + c]
                + sw01[s] * fb[(y1 * WF + x0) * CF + c]
                + sw11[s] * fb[(y1 * WF + x1) * CF + c];
        __half hi = __float2half(v);
        xh[s * 256 + c] = hi;
        xl[s * 256 + c] = __float2half(v - __half2float(hi));
    }
}

// ---------------------------------------------------------------------------
// Kernel 4: permute fc1 weights (hi only): W1h[j, s*256+c] = fc1_w[j, c*49+s]
// float4 loads, half2 stores.
// ---------------------------------------------------------------------------
__global__ void __launch_bounds__(256) permute_w1_kernel(const float* __restrict__ w1)
{
    __shared__ float sm[128 * 49];
    const int j = blockIdx.x >> 1;
    const int c0 = (blockIdx.x & 1) * 128;
    const int t = threadIdx.x;

    const float4* src4 = (const float4*)(w1 + (size_t)j * KDIM + (size_t)c0 * 49);
#pragma unroll
    for (int i = t; i < 1568; i += 256) ((float4*)sm)[i] = src4[i];
    __syncthreads();

    __half2* dh = (__half2*)(g_w1h + (size_t)j * KDIM);
    for (int e = t; e < 49 * 64; e += 256) {
        int s = e / 64, q = e % 64;
        float v0 = sm[(2 * q) * 49 + s];
        float v1 = sm[(2 * q + 1) * 49 + s];
        dh[s * 128 + (c0 >> 1) + q] = __floats2half2_rn(v0, v1);
    }
}

// ---------------------------------------------------------------------------
// Kernel 4b: fc2 weight fp32 -> fp16 (hi only).
// ---------------------------------------------------------------------------
__global__ void __launch_bounds__(256) convert_w2_kernel(const float* __restrict__ w2)
{
    int i = blockIdx.x * 256 + threadIdx.x;           // one float4 each
    float4 v = ((const float4*)w2)[i];
    __half2* d = (__half2*)g_w2h;
    d[2 * i]     = __floats2half2_rn(v.x, v.y);
    d[2 * i + 1] = __floats2half2_rn(v.z, v.w);
}

// ---------------------------------------------------------------------------
// Kernel 5: mma.sync GEMM, 2-term split (AhBh + AlBh), fp32 accum.
// C[m,n] = relu( sum_k A[m,k]*B[n,k] + bias[n] ),  C row stride = NFC.
// CTA tile 64(M) x 128(N), BK=64, 256 threads, 8 warps (warp tile 32x32),
// 3-stage cp.async pipeline, one __syncthreads per chunk.
// mode 0: write fp32 to Cf.  mode 1: write fp16 hi/lo to Ch/Cl.
// ---------------------------------------------------------------------------
#define RSTRIDE 144                       // (64+8) halves * 2B, kills LDSM conflicts
#define AH_OFF 0                          // 64 rows
#define AL_OFF (64 * RSTRIDE)             // 9216
#define BH_OFF (128 * RSTRIDE)            // 18432, B: 128 rows
#define STAGE_B (256 * RSTRIDE)           // 36864 B
#define GEMM_SMEM (3 * STAGE_B)           // 110592 B

__device__ __forceinline__ uint32_t smem_u32(const void* p) {
    uint32_t a;
    asm("{ .reg .u64 t; cvta.to.shared.u64 t, %1; cvt.u32.u64 %0, t; }" : "=r"(a) : "l"(p));
    return a;
}
__device__ __forceinline__ void cp16(uint32_t dst, const void* src) {
    asm volatile("cp.async.cg.shared.global [%0], [%1], 16;" :: "r"(dst), "l"(src) : "memory");
}
#define LDSM4(R, addr) \
    asm volatile("ldmatrix.sync.aligned.m8n8.x4.shared.b16 {%0,%1,%2,%3}, [%4];" \
                 : "=r"((R)[0]), "=r"((R)[1]), "=r"((R)[2]), "=r"((R)[3]) : "r"(addr))

__device__ __forceinline__ void mma16816(float* d, const uint32_t* a, const uint32_t* b) {
    asm volatile(
        "mma.sync.aligned.m16n8k16.row.col.f32.f16.f16.f32 "
        "{%0,%1,%2,%3}, {%4,%5,%6,%7}, {%8,%9}, {%0,%1,%2,%3};"
        : "+f"(d[0]), "+f"(d[1]), "+f"(d[2]), "+f"(d[3])
        : "r"(a[0]), "r"(a[1]), "r"(a[2]), "r"(a[3]), "r"(b[0]), "r"(b[1]));
}

__device__ __forceinline__ void load_chunk(
    uint32_t st, const __half* __restrict__ Ah, const __half* __restrict__ Al,
    const __half* __restrict__ Bh, int m0, int n0, int K, int k0, int t)
{
#pragma unroll
    for (int e = t; e < 512; e += 256) {           // A: 64 rows x 8 segs (hi+lo)
        int r = e >> 3, s = e & 7;
        size_t g = (size_t)(m0 + r) * K + k0 + s * 8;
        uint32_t d = (uint32_t)(r * RSTRIDE + s * 16);
        cp16(st + AH_OFF + d, Ah + g);
        cp16(st + AL_OFF + d, Al + g);
    }
#pragma unroll
    for (int e = t; e < 1024; e += 256) {          // B: 128 rows x 8 segs (hi only)
        int r = e >> 3, s = e & 7;
        size_t g = (size_t)(n0 + r) * K + k0 + s * 8;
        uint32_t d = (uint32_t)(r * RSTRIDE + s * 16);
        cp16(st + BH_OFF + d, Bh + g);
    }
}

__global__ void __launch_bounds__(256, 1) gemm_mma_kernel(
    const __half* __restrict__ Ah, const __half* __restrict__ Al,
    const __half* __restrict__ Bh,
    const float* __restrict__ bias, float* __restrict__ Cf,
    __half* __restrict__ Ch, __half* __restrict__ Cl, int K, int mode)
{
    extern __shared__ char smem[];
    const uint32_t sb = smem_u32(smem);
    const int t = threadIdx.x;
    const int m0 = blockIdx.y * 64;
    const int n0 = blockIdx.x * 128;

    const int w = t >> 5, l = t & 31;
    const int wm = (w >> 2) * 32;                 // warp M offset (0/32)
    const int wn = (w & 3) * 32;                  // warp N offset (0/32/64/96)
    const int a_m  = (l & 7) + ((l >> 3) & 1) * 8;
    const int a_ks = (l >> 4) * 16;
    const int b_n  = (l & 7) + (l >> 4) * 8;
    const int b_ks = ((l >> 3) & 1) * 16;

    float acc[2][4][4];
#pragma unroll
    for (int i = 0; i < 2; i++)
#pragma unroll
        for (int j = 0; j < 4; j++)
#pragma unroll
            for (int q = 0; q < 4; q++) acc[i][j][q] = 0.f;

    const int nit = K >> 6;
    load_chunk(sb, Ah, Al, Bh, m0, n0, K, 0, t);
    asm volatile("cp.async.commit_group;" ::: "memory");
    load_chunk(sb + STAGE_B, Ah, Al, Bh, m0, n0, K, 64, t);
    asm volatile("cp.async.commit_group;" ::: "memory");

    for (int i = 0; i < nit; i++) {
        if (i + 1 < nit) asm volatile("cp.async.wait_group 1;" ::: "memory");
        else             asm volatile("cp.async.wait_group 0;" ::: "memory");
        __syncthreads();

        const uint32_t st = sb + (uint32_t)(i % 3) * STAGE_B;
#pragma unroll
        for (int kk = 0; kk < 4; kk++) {
            const uint32_t kb = (uint32_t)(kk * 32);
            uint32_t rah[2][4], ral[2][4], rb[2][4];
#pragma unroll
            for (int mt = 0; mt < 2; mt++) {
                uint32_t row = (uint32_t)((wm + mt * 16 + a_m) * RSTRIDE) + kb + a_ks;
                LDSM4(rah[mt], st + AH_OFF + row);
                LDSM4(ral[mt], st + AL_OFF + row);
            }
#pragma unroll
            for (int np = 0; np < 2; np++) {
                uint32_t row = (uint32_t)((wn + np * 16 + b_n) * RSTRIDE) + kb + b_ks;
                LDSM4(rb[np], st + BH_OFF + row);
            }
#pragma unroll
            for (int mt = 0; mt < 2; mt++)
#pragma unroll
                for (int nt = 0; nt < 4; nt++) {
                    const uint32_t* bp = &rb[nt >> 1][(nt & 1) * 2];
                    mma16816(acc[mt][nt], rah[mt], bp);
                    mma16816(acc[mt][nt], ral[mt], bp);
                }
        }

        if (i + 2 < nit) {
            load_chunk(sb + (uint32_t)((i + 2) % 3) * STAGE_B, Ah, Al, Bh,
                       m0, n0, K, (i + 2) << 6, t);
            asm volatile("cp.async.commit_group;" ::: "memory");
        }
    }

    // epilogue: bias + relu, write
#pragma unroll
    for (int mt = 0; mt < 2; mt++) {
        const int mrow = m0 + wm + mt * 16 + (l >> 2);
#pragma unroll
        for (int nt = 0; nt < 4; nt++) {
            const int ncol = n0 + wn + nt * 8 + (l & 3) * 2;
            const float b0 = bias[ncol], b1 = bias[ncol + 1];
            float v0 = fmaxf(acc[mt][nt][0] + b0, 0.f);
            float v1 = fmaxf(acc[mt][nt][1] + b1, 0.f);
            float v2 = fmaxf(acc[mt][nt][2] + b0, 0.f);
            float v3 = fmaxf(acc[mt][nt][3] + b1, 0.f);
            size_t i0 = (size_t)mrow * NFC + ncol;
            size_t i1 = (size_t)(mrow + 8) * NFC + ncol;
            if (mode == 0) {
                Cf[i0] = v0; Cf[i0 + 1] = v1;
                Cf[i1] = v2; Cf[i1 + 1] = v3;
            } else {
                __half h0 = __float2half(v0), h1v = __float2half(v1);
                __half h2v = __float2half(v2), h3 = __float2half(v3);
                Ch[i0] = h0;  Ch[i0 + 1] = h1v;
                Ch[i1] = h2v; Ch[i1 + 1] = h3;
                Cl[i0] = __float2half(v0 - __half2float(h0));
                Cl[i0 + 1] = __float2half(v1 - __half2float(h1v));
                Cl[i1] = __float2half(v2 - __half2float(h2v));
                Cl[i1 + 1] = __float2half(v3 - __half2float(h3));
            }
        }
    }
}

// ---------------------------------------------------------------------------
// Kernel 6: heads. grid 800, 320 threads (10 warps = 10 outputs).
// ---------------------------------------------------------------------------
__global__ void __launch_bounds__(320) heads_kernel(
    const float* __restrict__ cls_w, const float* __restrict__ cls_b,
    const float* __restrict__ bbox_w, const float* __restrict__ bbox_b,
    float* __restrict__ out)
{
    const int n = blockIdx.x;
    const int warp = threadIdx.x >> 5;
    const int lane = threadIdx.x & 31;

    const float* W = (warp < 5) ? (cls_w + (size_t)warp * NFC)
                                : (bbox_w + (size_t)(warp - 5) * NFC);
    const float  bb = (warp < 5) ? cls_b[warp] : bbox_b[warp - 5];
    const float* hr = g_h2 + (size_t)n * NFC;

    float acc = 0.f;
    for (int k = lane; k < NFC; k += 32) acc += hr[k] * W[k];
#pragma unroll
    for (int o = 16; o > 0; o >>= 1) acc += __shfl_down_sync(0xffffffffu, acc, o);

    if (lane == 0) {
        float v = acc + bb;
        if (warp < 5) out[(size_t)n * 5 + warp] = v;
        else          out[4000 + (size_t)n * 5 + (warp - 5)] = v;
    }
}

// ---------------------------------------------------------------------------
extern "C" void kernel_launch(void* const* d_in, const int* in_sizes, int n_in,
                              void* d_out, int out_size)
{
    const float* images     = (const float*)d_in[0];
    const float* backbone_w = (const float*)d_in[1];
    const float* backbone_b = (const float*)d_in[2];
    const float* rpn_conv_w = (const float*)d_in[3];
    const float* rpn_conv_b = (const float*)d_in[4];
    // d_in[5], d_in[6]: obj head — dead code in the reference
    const float* delta_w    = (const float*)d_in[7];
    const float* delta_b    = (const float*)d_in[8];
    const float* fc1_w      = (const float*)d_in[9];
    const float* fc1_b      = (const float*)d_in[10];
    const float* fc2_w      = (const float*)d_in[11];
    const float* fc2_b      = (const float*)d_in[12];
    const float* cls_w      = (const float*)d_in[13];
    const float* cls_b      = (const float*)d_in[14];
    const float* bbox_w     = (const float*)d_in[15];
    const float* bbox_b     = (const float*)d_in[16];
    float* out = (float*)d_out;

    __half *xh, *xl, *w1h, *w2h, *h1h, *h1l;
    float *h2;
    cudaGetSymbolAddress((void**)&xh,  g_xh);
    cudaGetSymbolAddress((void**)&xl,  g_xl);
    cudaGetSymbolAddress((void**)&w1h, g_w1h);
    cudaGetSymbolAddress((void**)&w2h, g_w2h);
    cudaGetSymbolAddress((void**)&h1h, g_h1h);
    cudaGetSymbolAddress((void**)&h1l, g_h1l);
    cudaGetSymbolAddress((void**)&h2,  g_h2);

    static int smem_set = 0;
    if (!smem_set) {
        cudaFuncSetAttribute(gemm_mma_kernel,
                             cudaFuncAttributeMaxDynamicSharedMemorySize, GEMM_SMEM);
        smem_set = 1;
    }

    // 1. backbone + avgpool -> g_f (NHWC)
    backbone_kernel<<<dim3(32, 8), 256>>>(images, backbone_w, backbone_b);

    // 2. RPN (4 positions) + decode -> g_boxes
    rpn_decode_kernel<<<32, 256>>>(rpn_conv_w, rpn_conv_b, delta_w, delta_b);

    // 3. ROI align -> xh/xl (fp16 split, permuted k layout)
    roi_align_kernel<<<NBOX, 256>>>();

    // 4. weight prep (hi only)
    permute_w1_kernel<<<2048, 256>>>(fc1_w);
    convert_w2_kernel<<<(NFC * NFC) / 1024, 256>>>(fc2_w);

    // 5. fc1: (896 x 12544) @ (1024 x 12544)^T + bias, relu -> h1 (fp16 split)
    gemm_mma_kernel<<<dim3(NFC / 128, MPAD / 64), 256, GEMM_SMEM>>>(
        xh, xl, w1h, fc1_b, h2 /*unused*/, h1h, h1l, KDIM, 1);

    // 6. fc2: (896 x 1024) @ (1024 x 1024)^T + bias, relu -> h2 (fp32)
    gemm_mma_kernel<<<dim3(NFC / 128, MPAD / 64), 256, GEMM_SMEM>>>(
        h1h, h1l, w2h, fc2_b, h2, h1h /*unused*/, h1l /*unused*/, NFC, 0);

    // 7. heads -> out
    heads_kernel<<<NBOX, 320>>>(cls_w, cls_b, bbox_w, bbox_b, out);
}

// round 16
// speedup vs baseline: 1.9795x; 1.0043x over previous
#include <cuda_runtime.h>
#include <cuda_fp16.h>
#include <math.h>
#include <stdint.h>

// ---------------------------------------------------------------------------
// B=8, images 3x1024x1024, backbone conv 3x3 s16 p1 -> 64x64, avgpool2 -> 32x32
// f: (8,32,32,256) NHWC. Only h=0, w=0..3 of the RPN matter (first 100 props).
// ROI align: 800 boxes -> x (800,12544), k' = s*256+c permutation, fp16 hi/lo.
// fc1/fc2 on mma.sync tensor cores with 2-term split: AhBh + AlBh (weights
// rounded once to fp16; dropped AhBl term is a ~1.4e-4 random-walk error,
// inside the 1e-3 gate). tcgen05 is unavailable: toolchain targets sm_103.
// Output: class_logits (800x5) then obb_preds (800x5) = 8000 floats.
// ---------------------------------------------------------------------------

#define BATCH 8
#define CF 256
#define HF 32
#define WF 32
#define NPROP 100
#define NBOX (BATCH * NPROP)   // 800
#define KDIM (CF * 49)         // 12544
#define MPAD 896               // 14 * 64
#define NFC 1024

__device__ float g_f[BATCH * HF * WF * CF];          // NHWC feature map
__device__ float g_boxes[NBOX * 5];
__device__ __half g_xh[MPAD * KDIM];                 // pooled hi (rows 800.. stay 0)
__device__ __half g_xl[MPAD * KDIM];                 // pooled lo
__device__ __half g_w1h[NFC * KDIM];                 // permuted fc1 weights (hi only)
__device__ __half g_w2h[NFC * NFC];                  // fc2 weights (hi only)
__device__ __half g_h1h[MPAD * NFC];
__device__ __half g_h1l[MPAD * NFC];
__device__ float g_h2[MPAD * NFC];

// ---------------------------------------------------------------------------
// Kernel 1: backbone conv (3x3, stride16, pad1) + 2x2 avgpool, fused. NHWC out.
// ---------------------------------------------------------------------------
__global__ void __launch_bounds__(256) backbone_kernel(
    const float* __restrict__ images, const float* __restrict__ wconv,
    const float* __restrict__ bconv)
{
    __shared__ float in_s[3][6][192];
    const int ph = blockIdx.x;
    const int b  = blockIdx.y;
    const int t  = threadIdx.x;

    for (int e = t; e < 3 * 6 * 192; e += 256) {
        int ch = e / 1152;
        int r  = (e / 192) % 6;
        int q  = e % 192;
        int ow = q / 3, kx = q % 3;
        int row = (r < 3) ? (32 * ph - 1 + r) : (32 * ph + 15 + (r - 3));
        int col = 16 * ow + kx - 1;
        float v = 0.f;
        if (row >= 0 && col >= 0)
            v = images[(((size_t)b * 3 + ch) * 1024 + row) * 1024 + col];
        in_s[ch][r][q] = v;
    }
    __syncthreads();

    const int oc = t;
    float wr[27];
#pragma unroll
    for (int j = 0; j < 27; j++) wr[j] = wconv[oc * 27 + j];
    const float bias = bconv[oc];

    for (int pw = 0; pw < 32; pw++) {
        float acc = 0.f;
#pragma unroll
        for (int sub = 0; sub < 4; sub++) {
            int r6b = (sub >> 1) * 3;
            int owp = 2 * pw + (sub & 1);
#pragma unroll
            for (int ch = 0; ch < 3; ch++)
#pragma unroll
                for (int ky = 0; ky < 3; ky++)
#pragma unroll
                    for (int kx = 0; kx < 3; kx++)
                        acc += wr[ch * 9 + ky * 3 + kx] * in_s[ch][r6b + ky][owp * 3 + kx];
        }
        g_f[(((size_t)b * HF + ph) * WF + pw) * CF + oc] = acc * 0.25f + bias;
    }
}

// ---------------------------------------------------------------------------
// Kernel 2: RPN conv (only h=0, w=0..3) + delta head + proposal decode.
// ---------------------------------------------------------------------------
__global__ void __launch_bounds__(256) rpn_decode_kernel(
    const float* __restrict__ rpn_w, const float* __restrict__ rpn_b,
    const float* __restrict__ delta_w, const float* __restrict__ delta_b)
{
    __shared__ float fin[2][3][256];
    __shared__ float t_s[256];
    __shared__ float d_s[135];

    const int b = blockIdx.x >> 2;
    const int w = blockIdx.x & 3;
    const int t = threadIdx.x;

    for (int e = t; e < 2 * 3 * 256; e += 256) {
        int iy = e / 768;
        int rem = e % 768;
        int cx = rem / 256;
        int c  = rem % 256;
        int col = w + cx - 1;
        float v = 0.f;
        if (col >= 0 && col < WF)
            v = g_f[(((size_t)b * HF + iy) * WF + col) * CF + c];
        fin[iy][cx][c] = v;
    }
    __syncthreads();

    {
        const int oc = t;
        float acc = rpn_b[oc];
        for (int c = 0; c < 256; c++) {
            const float* wp = rpn_w + ((size_t)oc * 256 + c) * 9;
#pragma unroll
            for (int ky = 1; ky < 3; ky++)
#pragma unroll
                for (int kx = 0; kx < 3; kx++)
                    acc += wp[ky * 3 + kx] * fin[ky - 1][kx][c];
        }
        t_s[oc] = fmaxf(acc, 0.f);
    }
    __syncthreads();

    if (t < 135) {
        float acc = delta_b[t];
        const float* wp = delta_w + (size_t)t * 256;
        for (int c = 0; c < 256; c++) acc += wp[c] * t_s[c];
        d_s[t] = acc;
    }
    __syncthreads();

    if (t < 27) {
        int a = t;
        int p = w * 27 + a;
        if (p < NPROP) {
            int si = a / 9, ri = (a % 9) / 3, angi = a % 3;
            float scale = 32.f * (float)(1 << si);
            float sr = (ri == 0) ? 0.70710678118654752f : (ri == 1 ? 1.f : 1.41421356237309505f);
            float aw = scale * sr;
            float ah = scale / sr;
            float aang = 45.f * (float)angi;
            float acx = 32.f * (float)w;
            float d0 = d_s[a * 5 + 0], d1 = d_s[a * 5 + 1], d2 = d_s[a * 5 + 2];
            float d3 = d_s[a * 5 + 3], d4 = d_s[a * 5 + 4];
            float* bx = g_boxes + ((size_t)b * NPROP + p) * 5;
            bx[0] = d0 * aw + acx;
            bx[1] = d1 * ah;
            bx[2] = expf(d2) * aw;
            bx[3] = expf(d3) * ah;
            bx[4] = aang + d4;
        }
    }
}

// ---------------------------------------------------------------------------
// Kernel 3: rotated ROI align -> fp16 hi/lo split, k' = s*256+c layout.
// ---------------------------------------------------------------------------
__global__ void __launch_bounds__(256) roi_align_kernel()
{
    __shared__ int   sx0[49], sy0[49], sx1[49], sy1[49];
    __shared__ float sw00[49], sw10[49], sw01[49], sw11[49];

    const int n = blockIdx.x;
    const int b = n / NPROP;
    const int t = threadIdx.x;

    if (t < 49) {
        int py = t / 7, px = t % 7;
        const float* bx = g_boxes + (size_t)n * 5;
        float cx = bx[0], cy = bx[1], w = bx[2], h = bx[3], ang = bx[4];
        float ar = -ang * 0.017453292519943295f;
        float cc = cosf(ar), ss = sinf(ar);
        float t00 = w * (1.f / WF) * cc;
        float t01 = -h * (1.f / HF) * ss;
        float t02 = 2.f * cx / WF - 1.f;
        float t10 = w * (1.f / WF) * ss;
        float t11 = h * (1.f / HF) * cc;
        float t12 = 2.f * cy / HF - 1.f;
        float xs = (2.f * px + 1.f) / 7.f - 1.f;
        float ys = (2.f * py + 1.f) / 7.f - 1.f;
        float gx = t00 * xs + t01 * ys + t02;
        float gy = t10 * xs + t11 * ys + t12;
        float ix = ((gx + 1.f) * WF - 1.f) * 0.5f;
        float iy = ((gy + 1.f) * HF - 1.f) * 0.5f;
        float x0f = floorf(ix), y0f = floorf(iy);
        float wx = ix - x0f, wy = iy - y0f;
        int x0 = (int)x0f, y0 = (int)y0f;
        int x1 = x0 + 1, y1 = y0 + 1;
        float vx0 = (x0 >= 0 && x0 < WF) ? 1.f : 0.f;
        float vx1 = (x1 >= 0 && x1 < WF) ? 1.f : 0.f;
        float vy0 = (y0 >= 0 && y0 < HF) ? 1.f : 0.f;
        float vy1 = (y1 >= 0 && y1 < HF) ? 1.f : 0.f;
        sw00[t] = (1.f - wx) * (1.f - wy) * vx0 * vy0;
        sw10[t] = wx * (1.f - wy) * vx1 * vy0;
        sw01[t] = (1.f - wx) * wy * vx0 * vy1;
        sw11[t] = wx * wy * vx1 * vy1;
        sx0[t] = min(max(x0, 0), WF - 1);
        sx1[t] = min(max(x1, 0), WF - 1);
        sy0[t] = min(max(y0, 0), HF - 1);
        sy1[t] = min(max(y1, 0), HF - 1);
    }
    __syncthreads();

    const int c = t;
    const float* fb = g_f + (size_t)b * HF * WF * CF;
    __half* xh = g_xh + (size_t)n * KDIM;
    __half* xl = g_xl + (size_t)n * KDIM;
#pragma unroll 7
    for (int s = 0; s < 49; s++) {
        int x0 = sx0[s], x1 = sx1[s], y0 = sy0[s], y1 = sy1[s];
        float v = sw00[s] * fb[(y0 * WF + x0) * CF + c]
                + sw10[s] * fb[(y0 * WF + x1) * CF + c]
                + sw01[s] * fb[(y1 * WF + x0) * CF + c]
                + sw11[s] * fb[(y1 * WF + x1) * CF + c];
        __half hi = __float2half(v);
        xh[s * 256 + c] = hi;
        xl[s * 256 + c] = __float2half(v - __half2float(hi));
    }
}

// ---------------------------------------------------------------------------
// Kernel 4: permute fc1 weights (hi only): W1h[j, s*256+c] = fc1_w[j, c*49+s]
// float4 loads, half2 stores.
// ---------------------------------------------------------------------------
__global__ void __launch_bounds__(256) permute_w1_kernel(const float* __restrict__ w1)
{
    __shared__ float sm[128 * 49];
    const int j = blockIdx.x >> 1;
    const int c0 = (blockIdx.x & 1) * 128;
    const int t = threadIdx.x;

    const float4* src4 = (const float4*)(w1 + (size_t)j * KDIM + (size_t)c0 * 49);
#pragma unroll
    for (int i = t; i < 1568; i += 256) ((float4*)sm)[i] = src4[i];
    __syncthreads();

    __half2* dh = (__half2*)(g_w1h + (size_t)j * KDIM);
    for (int e = t; e < 49 * 64; e += 256) {
        int s = e / 64, q = e % 64;
        float v0 = sm[(2 * q) * 49 + s];
        float v1 = sm[(2 * q + 1) * 49 + s];
        dh[s * 128 + (c0 >> 1) + q] = __floats2half2_rn(v0, v1);
    }
}

// ---------------------------------------------------------------------------
// Kernel 4b: fc2 weight fp32 -> fp16 (hi only).
// ---------------------------------------------------------------------------
__global__ void __launch_bounds__(256) convert_w2_kernel(const float* __restrict__ w2)
{
    int i = blockIdx.x * 256 + threadIdx.x;           // one float4 each
    float4 v = ((const float4*)w2)[i];
    __half2* d = (__half2*)g_w2h;
    d[2 * i]     = __floats2half2_rn(v.x, v.y);
    d[2 * i + 1] = __floats2half2_rn(v.z, v.w);
}

// ---------------------------------------------------------------------------
// Kernel 5: mma.sync GEMM, 2-term split (AhBh + AlBh), fp32 accum.
// C[m,n] = relu( sum_k A[m,k]*B[n,k] + bias[n] ),  C row stride = NFC.
// CTA tile 64(M) x 128(N), BK=64, 256 threads, 8 warps (warp tile 32x32),
// 3-stage cp.async pipeline, one __syncthreads per chunk.
// mode 0: write fp32 to Cf.  mode 1: write fp16 hi/lo to Ch/Cl.
// ---------------------------------------------------------------------------
#define RSTRIDE 144                       // (64+8) halves * 2B, kills LDSM conflicts
#define AH_OFF 0                          // 64 rows
#define AL_OFF (64 * RSTRIDE)             // 9216
#define BH_OFF (128 * RSTRIDE)            // 18432, B: 128 rows
#define STAGE_B (256 * RSTRIDE)           // 36864 B
#define GEMM_SMEM (3 * STAGE_B)           // 110592 B

__device__ __forceinline__ uint32_t smem_u32(const void* p) {
    uint32_t a;
    asm("{ .reg .u64 t; cvta.to.shared.u64 t, %1; cvt.u32.u64 %0, t; }" : "=r"(a) : "l"(p));
    return a;
}
__device__ __forceinline__ void cp16(uint32_t dst, const void* src) {
    asm volatile("cp.async.cg.shared.global [%0], [%1], 16;" :: "r"(dst), "l"(src) : "memory");
}
#define LDSM4(R, addr) \
    asm volatile("ldmatrix.sync.aligned.m8n8.x4.shared.b16 {%0,%1,%2,%3}, [%4];" \
                 : "=r"((R)[0]), "=r"((R)[1]), "=r"((R)[2]), "=r"((R)[3]) : "r"(addr))

__device__ __forceinline__ void mma16816(float* d, const uint32_t* a, const uint32_t* b) {
    asm volatile(
        "mma.sync.aligned.m16n8k16.row.col.f32.f16.f16.f32 "
        "{%0,%1,%2,%3}, {%4,%5,%6,%7}, {%8,%9}, {%0,%1,%2,%3};"
        : "+f"(d[0]), "+f"(d[1]), "+f"(d[2]), "+f"(d[3])
        : "r"(a[0]), "r"(a[1]), "r"(a[2]), "r"(a[3]), "r"(b[0]), "r"(b[1]));
}

__device__ __forceinline__ void load_chunk(
    uint32_t st, const __half* __restrict__ Ah, const __half* __restrict__ Al,
    const __half* __restrict__ Bh, int m0, int n0, int K, int k0, int t)
{
#pragma unroll
    for (int e = t; e < 512; e += 256) {           // A: 64 rows x 8 segs (hi+lo)
        int r = e >> 3, s = e & 7;
        size_t g = (size_t)(m0 + r) * K + k0 + s * 8;
        uint32_t d = (uint32_t)(r * RSTRIDE + s * 16);
        cp16(st + AH_OFF + d, Ah + g);
        cp16(st + AL_OFF + d, Al + g);
    }
#pragma unroll
    for (int e = t; e < 1024; e += 256) {          // B: 128 rows x 8 segs (hi only)
        int r = e >> 3, s = e & 7;
        size_t g = (size_t)(n0 + r) * K + k0 + s * 8;
        uint32_t d = (uint32_t)(r * RSTRIDE + s * 16);
        cp16(st + BH_OFF + d, Bh + g);
    }
}

__global__ void __launch_bounds__(256, 1) gemm_mma_kernel(
    const __half* __restrict__ Ah, const __half* __restrict__ Al,
    const __half* __restrict__ Bh,
    const float* __restrict__ bias, float* __restrict__ Cf,
    __half* __restrict__ Ch, __half* __restrict__ Cl, int K, int mode)
{
    extern __shared__ char smem[];
    const uint32_t sb = smem_u32(smem);
    const int t = threadIdx.x;
    const int m0 = blockIdx.y * 64;
    const int n0 = blockIdx.x * 128;

    const int w = t >> 5, l = t & 31;
    const int wm = (w >> 2) * 32;                 // warp M offset (0/32)
    const int wn = (w & 3) * 32;                  // warp N offset (0/32/64/96)
    const int a_m  = (l & 7) + ((l >> 3) & 1) * 8;
    const int a_ks = (l >> 4) * 16;
    const int b_n  = (l & 7) + (l >> 4) * 8;
    const int b_ks = ((l >> 3) & 1) * 16;

    float acc[2][4][4];
#pragma unroll
    for (int i = 0; i < 2; i++)
#pragma unroll
        for (int j = 0; j < 4; j++)
#pragma unroll
            for (int q = 0; q < 4; q++) acc[i][j][q] = 0.f;

    const int nit = K >> 6;
    load_chunk(sb, Ah, Al, Bh, m0, n0, K, 0, t);
    asm volatile("cp.async.commit_group;" ::: "memory");
    load_chunk(sb + STAGE_B, Ah, Al, Bh, m0, n0, K, 64, t);
    asm volatile("cp.async.commit_group;" ::: "memory");

    for (int i = 0; i < nit; i++) {
        if (i + 1 < nit) asm volatile("cp.async.wait_group 1;" ::: "memory");
        else             asm volatile("cp.async.wait_group 0;" ::: "memory");
        __syncthreads();

        const uint32_t st = sb + (uint32_t)(i % 3) * STAGE_B;
#pragma unroll
        for (int kk = 0; kk < 4; kk++) {
            const uint32_t kb = (uint32_t)(kk * 32);
            uint32_t rah[2][4], ral[2][4], rb[2][4];
#pragma unroll
            for (int mt = 0; mt < 2; mt++) {
                uint32_t row = (uint32_t)((wm + mt * 16 + a_m) * RSTRIDE) + kb + a_ks;
                LDSM4(rah[mt], st + AH_OFF + row);
                LDSM4(ral[mt], st + AL_OFF + row);
            }
#pragma unroll
            for (int np = 0; np < 2; np++) {
                uint32_t row = (uint32_t)((wn + np * 16 + b_n) * RSTRIDE) + kb + b_ks;
                LDSM4(rb[np], st + BH_OFF + row);
            }
#pragma unroll
            for (int mt = 0; mt < 2; mt++)
#pragma unroll
                for (int nt = 0; nt < 4; nt++) {
                    const uint32_t* bp = &rb[nt >> 1][(nt & 1) * 2];
                    mma16816(acc[mt][nt], rah[mt], bp);
                    mma16816(acc[mt][nt], ral[mt], bp);
                }
        }

        if (i + 2 < nit) {
            load_chunk(sb + (uint32_t)((i + 2) % 3) * STAGE_B, Ah, Al, Bh,
                       m0, n0, K, (i + 2) << 6, t);
            asm volatile("cp.async.commit_group;" ::: "memory");
        }
    }

    // epilogue: bias + relu, write
#pragma unroll
    for (int mt = 0; mt < 2; mt++) {
        const int mrow = m0 + wm + mt * 16 + (l >> 2);
#pragma unroll
        for (int nt = 0; nt < 4; nt++) {
            const int ncol = n0 + wn + nt * 8 + (l & 3) * 2;
            const float b0 = bias[ncol], b1 = bias[ncol + 1];
            float v0 = fmaxf(acc[mt][nt][0] + b0, 0.f);
            float v1 = fmaxf(acc[mt][nt][1] + b1, 0.f);
            float v2 = fmaxf(acc[mt][nt][2] + b0, 0.f);
            float v3 = fmaxf(acc[mt][nt][3] + b1, 0.f);
            size_t i0 = (size_t)mrow * NFC + ncol;
            size_t i1 = (size_t)(mrow + 8) * NFC + ncol;
            if (mode == 0) {
                Cf[i0] = v0; Cf[i0 + 1] = v1;
                Cf[i1] = v2; Cf[i1 + 1] = v3;
            } else {
                __half h0 = __float2half(v0), h1v = __float2half(v1);
                __half h2v = __float2half(v2), h3 = __float2half(v3);
                Ch[i0] = h0;  Ch[i0 + 1] = h1v;
                Ch[i1] = h2v; Ch[i1 + 1] = h3;
                Cl[i0] = __float2half(v0 - __half2float(h0));
                Cl[i0 + 1] = __float2half(v1 - __half2float(h1v));
                Cl[i1] = __float2half(v2 - __half2float(h2v));
                Cl[i1 + 1] = __float2half(v3 - __half2float(h3));
            }
        }
    }
}

// ---------------------------------------------------------------------------
// Kernel 6: heads. grid 800, 320 threads (10 warps = 10 outputs).
// ---------------------------------------------------------------------------
__global__ void __launch_bounds__(320) heads_kernel(
    const float* __restrict__ cls_w, const float* __restrict__ cls_b,
    const float* __restrict__ bbox_w, const float* __restrict__ bbox_b,
    float* __restrict__ out)
{
    const int n = blockIdx.x;
    const int warp = threadIdx.x >> 5;
    const int lane = threadIdx.x & 31;

    const float* W = (warp < 5) ? (cls_w + (size_t)warp * NFC)
                                : (bbox_w + (size_t)(warp - 5) * NFC);
    const float  bb = (warp < 5) ? cls_b[warp] : bbox_b[warp - 5];
    const float* hr = g_h2 + (size_t)n * NFC;

    float acc = 0.f;
    for (int k = lane; k < NFC; k += 32) acc += hr[k] * W[k];
#pragma unroll
    for (int o = 16; o > 0; o >>= 1) acc += __shfl_down_sync(0xffffffffu, acc, o);

    if (lane == 0) {
        float v = acc + bb;
        if (warp < 5) out[(size_t)n * 5 + warp] = v;
        else          out[4000 + (size_t)n * 5 + (warp - 5)] = v;
    }
}

// ---------------------------------------------------------------------------
extern "C" void kernel_launch(void* const* d_in, const int* in_sizes, int n_in,
                              void* d_out, int out_size)
{
    const float* images     = (const float*)d_in[0];
    const float* backbone_w = (const float*)d_in[1];
    const float* backbone_b = (const float*)d_in[2];
    const float* rpn_conv_w = (const float*)d_in[3];
    const float* rpn_conv_b = (const float*)d_in[4];
    // d_in[5], d_in[6]: obj head — dead code in the reference
    const float* delta_w    = (const float*)d_in[7];
    const float* delta_b    = (const float*)d_in[8];
    const float* fc1_w      = (const float*)d_in[9];
    const float* fc1_b      = (const float*)d_in[10];
    const float* fc2_w      = (const float*)d_in[11];
    const float* fc2_b      = (const float*)d_in[12];
    const float* cls_w      = (const float*)d_in[13];
    const float* cls_b      = (const float*)d_in[14];
    const float* bbox_w     = (const float*)d_in[15];
    const float* bbox_b     = (const float*)d_in[16];
    float* out = (float*)d_out;

    __half *xh, *xl, *w1h, *w2h, *h1h, *h1l;
    float *h2;
    cudaGetSymbolAddress((void**)&xh,  g_xh);
    cudaGetSymbolAddress((void**)&xl,  g_xl);
    cudaGetSymbolAddress((void**)&w1h, g_w1h);
    cudaGetSymbolAddress((void**)&w2h, g_w2h);
    cudaGetSymbolAddress((void**)&h1h, g_h1h);
    cudaGetSymbolAddress((void**)&h1l, g_h1l);
    cudaGetSymbolAddress((void**)&h2,  g_h2);

    static int smem_set = 0;
    if (!smem_set) {
        cudaFuncSetAttribute(gemm_mma_kernel,
                             cudaFuncAttributeMaxDynamicSharedMemorySize, GEMM_SMEM);
        smem_set = 1;
    }

    // 1. backbone + avgpool -> g_f (NHWC)
    backbone_kernel<<<dim3(32, 8), 256>>>(images, backbone_w, backbone_b);

    // 2. RPN (4 positions) + decode -> g_boxes
    rpn_decode_kernel<<<32, 256>>>(rpn_conv_w, rpn_conv_b, delta_w, delta_b);

    // 3. ROI align -> xh/xl (fp16 split, permuted k layout)
    roi_align_kernel<<<NBOX, 256>>>();

    // 4. weight prep (hi only)
    permute_w1_kernel<<<2048, 256>>>(fc1_w);
    convert_w2_kernel<<<(NFC * NFC) / 1024, 256>>>(fc2_w);

    // 5. fc1: (896 x 12544) @ (1024 x 12544)^T + bias, relu -> h1 (fp16 split)
    gemm_mma_kernel<<<dim3(NFC / 128, MPAD / 64), 256, GEMM_SMEM>>>(
        xh, xl, w1h, fc1_b, h2 /*unused*/, h1h, h1l, KDIM, 1);

    // 6. fc2: (896 x 1024) @ (1024 x 1024)^T + bias, relu -> h2 (fp32)
    gemm_mma_kernel<<<dim3(NFC / 128, MPAD / 64), 256, GEMM_SMEM>>>(
        h1h, h1l, w2h, fc2_b, h2, h1h /*unused*/, h1l /*unused*/, NFC, 0);

    // 7. heads -> out
    heads_kernel<<<NBOX, 320>>>(cls_w, cls_b, bbox_w, bbox_b, out);
}